// round 15
// baseline (speedup 1.0000x reference)
#include <cuda_runtime.h>
#include <cuda_bf16.h>
#include <cuda_fp16.h>
#include <cstdint>

#define N_NODES 50000
#define N_PAD   50048            // 391 * 128
#define N_EDGES 1600000
#define D_FEAT  512
#define UNITS   512

// ---------------- static device scratch (no runtime allocation) ----------
__device__ __half g_hh[(size_t)N_PAD * UNITS];      // h = X @ W (fp16)
__device__ __half g_Wt[(size_t)UNITS * D_FEAT];     // W^T in fp16: [n][k]
__device__ int   g_deg[N_NODES];
__device__ int   g_off[N_NODES + 1];
__device__ int   g_rank[N_EDGES];                   // per-edge within-dst rank
__device__ int2  g_sorted[N_EDGES];

#define SCAN_T  512
#define SCAN_NB 98                // ceil(50000 / 512)
__device__ int g_blk_flag[SCAN_NB];   // 0=invalid 1=aggregate 2=prefix
__device__ int g_blk_agg[SCAN_NB];
__device__ int g_blk_pref[SCAN_NB];

// ---------------- helpers ------------------------------------------------
__device__ __forceinline__ uint32_t smem_u32(const void* p) {
    uint32_t a;
    asm("{ .reg .u64 t; cvta.to.shared.u64 t, %1; cvt.u32.u64 %0, t; }"
        : "=r"(a) : "l"(p));
    return a;
}
__device__ __forceinline__ void cp_async16(uint32_t dst, const void* src) {
    asm volatile("cp.async.cg.shared.global [%0], [%1], 16;" :: "r"(dst), "l"(src));
}
#define CP_COMMIT() asm volatile("cp.async.commit_group;" ::: "memory")
#define CP_WAIT(n)  asm volatile("cp.async.wait_group %0;" :: "n"(n) : "memory")

#define LDMATRIX_X4(r0, r1, r2, r3, addr) \
    asm volatile("ldmatrix.sync.aligned.m8n8.x4.shared.b16 {%0,%1,%2,%3}, [%4];" \
        : "=r"(r0), "=r"(r1), "=r"(r2), "=r"(r3) : "r"(addr))

__device__ __forceinline__ void mma16816_f16(float* d, const uint32_t* a,
                                             uint32_t b0, uint32_t b1) {
    asm volatile(
        "mma.sync.aligned.m16n8k16.row.col.f32.f16.f16.f32 "
        "{%0,%1,%2,%3}, {%4,%5,%6,%7}, {%8,%9}, {%0,%1,%2,%3};"
        : "+f"(d[0]), "+f"(d[1]), "+f"(d[2]), "+f"(d[3])
        : "r"(a[0]), "r"(a[1]), "r"(a[2]), "r"(a[3]), "r"(b0), "r"(b1));
}

// Per-block int64/int32 detection (warp 0, broadcast via smem).
__device__ __forceinline__ int block_detect_is64(const void* src_raw) {
    __shared__ int s_is64;
    if (threadIdx.x < 32) {
        const long long* p = (const long long*)src_raw;
        const long long v0 = p[threadIdx.x * 2];
        const long long v1 = p[threadIdx.x * 2 + 1];
        const bool bad = (v0 < 0) || (v0 >= N_NODES) || (v1 < 0) || (v1 >= N_NODES);
        const unsigned m = __ballot_sync(0xFFFFFFFFu, bad);
        if (threadIdx.x == 0) s_is64 = (m == 0) ? 1 : 0;
    }
    __syncthreads();
    return s_is64;
}

// ---------------------------------------------------------------------------
// CSR build
// ---------------------------------------------------------------------------
__global__ __launch_bounds__(256) void zero_kernel()
{
    const int t = blockIdx.x * blockDim.x + threadIdx.x;
    for (int i = t; i < N_NODES; i += gridDim.x * blockDim.x)
        g_deg[i] = 0;
    if (t < SCAN_NB) g_blk_flag[t] = 0;
    if (t == 0) g_off[N_NODES] = N_EDGES;
}

// Histogram: 4 edges per thread-iteration; saves each edge's within-dst rank
// (the atomicAdd return) so placement needs no atomics.
__global__ __launch_bounds__(256) void hist_kernel(const void* __restrict__ dst_raw)
{
    const int is64 = block_detect_is64(dst_raw);
    const int nquad = N_EDGES / 4;           // 400000 (exact)
    for (int i = blockIdx.x * blockDim.x + threadIdx.x;
         i < nquad; i += gridDim.x * blockDim.x) {
        int d0, d1, d2, d3;
        if (is64) {
            const longlong2 a = ((const longlong2*)dst_raw)[2 * i];
            const longlong2 b = ((const longlong2*)dst_raw)[2 * i + 1];
            d0 = (int)a.x; d1 = (int)a.y; d2 = (int)b.x; d3 = (int)b.y;
        } else {
            const int4 q = ((const int4*)dst_raw)[i];
            d0 = q.x; d1 = q.y; d2 = q.z; d3 = q.w;
        }
        int4 r;
        r.x = atomicAdd(&g_deg[d0], 1);
        r.y = atomicAdd(&g_deg[d1], 1);
        r.z = atomicAdd(&g_deg[d2], 1);
        r.w = atomicAdd(&g_deg[d3], 1);
        ((int4*)g_rank)[i] = r;
    }
}

// Decoupled-lookback exclusive scan, 512 threads x 98 blocks,
// warp-windowed lookback.
__global__ __launch_bounds__(SCAN_T) void scan_lookback_kernel()
{
    __shared__ int warp_sums[16];
    __shared__ int s_base;

    const int b = blockIdx.x;
    const int tid = threadIdx.x;
    const int i = b * SCAN_T + tid;
    const int lane = tid & 31;
    const int w = tid >> 5;

    const int v = (i < N_NODES) ? g_deg[i] : 0;

    int incl = v;
#pragma unroll
    for (int o = 1; o < 32; o <<= 1) {
        int t = __shfl_up_sync(0xFFFFFFFFu, incl, o);
        if (lane >= o) incl += t;
    }
    if (lane == 31) warp_sums[w] = incl;
    __syncthreads();

    if (w == 0) {
        int ws = (lane < 16) ? warp_sums[lane] : 0;
        int wincl = ws;
#pragma unroll
        for (int o = 1; o < 16; o <<= 1) {
            int t = __shfl_up_sync(0xFFFFFFFFu, wincl, o);
            if (lane >= o) wincl += t;
        }
        if (lane < 16) warp_sums[lane] = wincl - ws;
        const int total = __shfl_sync(0xFFFFFFFFu, wincl, 15);

        volatile int* vflag = g_blk_flag;
        volatile int* vagg  = g_blk_agg;
        volatile int* vpref = g_blk_pref;

        if (b == 0) {
            if (lane == 0) {
                g_blk_agg[0] = total;
                g_blk_pref[0] = total;
                __threadfence();
                vflag[0] = 2;
                s_base = 0;
            }
        } else {
            if (lane == 0) {
                g_blk_agg[b] = total;
                __threadfence();
                vflag[b] = 1;
            }
            int running = 0;
            int p = b - 1;
            while (true) {
                const int idx = p - lane;
                int f;
                do {
                    f = (idx >= 0) ? vflag[idx] : 2;
                } while (__any_sync(0xFFFFFFFFu, f == 0));
                const unsigned pm = __ballot_sync(0xFFFFFFFFu, f == 2);
                const int firstP = __ffs(pm) - 1;
                int contrib = 0;
                if (idx >= 0) {
                    if (pm == 0) {
                        contrib = vagg[idx];
                    } else if (lane < firstP) {
                        contrib = vagg[idx];
                    } else if (lane == firstP) {
                        contrib = vpref[idx];
                    }
                }
#pragma unroll
                for (int o = 16; o > 0; o >>= 1)
                    contrib += __shfl_down_sync(0xFFFFFFFFu, contrib, o);
                contrib = __shfl_sync(0xFFFFFFFFu, contrib, 0);
                running += contrib;
                if (pm != 0) break;
                p -= 32;
            }
            if (lane == 0) {
                s_base = running;
                g_blk_pref[b] = running + total;
                __threadfence();
                vflag[b] = 2;
            }
        }
    }
    __syncthreads();

    if (i < N_NODES)
        g_off[i] = s_base + warp_sums[w] + incl - v;
}

// Placement: ATOMIC-FREE. pos = off[dst] + precomputed rank. 4 edges/iter,
// all stores independent -> fully pipelined.
__global__ __launch_bounds__(256) void place_kernel(
    const void* __restrict__ src_raw, const void* __restrict__ dst_raw,
    const float* __restrict__ ew)
{
    const int is64 = block_detect_is64(src_raw);
    const int nquad = N_EDGES / 4;           // 400000 (exact)
    for (int i = blockIdx.x * blockDim.x + threadIdx.x;
         i < nquad; i += gridDim.x * blockDim.x) {
        int s0, s1, s2, s3, d0, d1, d2, d3;
        if (is64) {
            const longlong2 sa = ((const longlong2*)src_raw)[2 * i];
            const longlong2 sb = ((const longlong2*)src_raw)[2 * i + 1];
            const longlong2 da = ((const longlong2*)dst_raw)[2 * i];
            const longlong2 db = ((const longlong2*)dst_raw)[2 * i + 1];
            s0 = (int)sa.x; s1 = (int)sa.y; s2 = (int)sb.x; s3 = (int)sb.y;
            d0 = (int)da.x; d1 = (int)da.y; d2 = (int)db.x; d3 = (int)db.y;
        } else {
            const int4 sv = ((const int4*)src_raw)[i];
            const int4 dv = ((const int4*)dst_raw)[i];
            s0 = sv.x; s1 = sv.y; s2 = sv.z; s3 = sv.w;
            d0 = dv.x; d1 = dv.y; d2 = dv.z; d3 = dv.w;
        }
        const float4 wv = ((const float4*)ew)[i];
        const int4 rv = ((const int4*)g_rank)[i];
        g_sorted[g_off[d0] + rv.x] = make_int2(s0, __float_as_int(wv.x));
        g_sorted[g_off[d1] + rv.y] = make_int2(s1, __float_as_int(wv.y));
        g_sorted[g_off[d2] + rv.z] = make_int2(s2, __float_as_int(wv.z));
        g_sorted[g_off[d3] + rv.w] = make_int2(s3, __float_as_int(wv.w));
    }
}

// ---------------------------------------------------------------------------
// Prep: W^T fp16 (tiny; X conversion is fused into the GEMM).
// ---------------------------------------------------------------------------
__global__ __launch_bounds__(256) void conv_W_kernel(const float* __restrict__ W)
{
    for (int i = blockIdx.x * blockDim.x + threadIdx.x;
         i < UNITS * D_FEAT; i += gridDim.x * blockDim.x) {
        const int n = i >> 9, k = i & 511;
        g_Wt[i] = __float2half_rn(W[(size_t)k * UNITS + n]);
    }
}

// ---------------------------------------------------------------------------
// fp16 mma.sync GEMM with fused fp32->fp16 A conversion.
// h = X @ Wt^T  (fp32 accumulate, fp16 store). CTA tile 128x256x32.
// ---------------------------------------------------------------------------
#define BM 128
#define BN 256
#define BK 32
#define PAD 40
#define ABUF (BM * PAD * 2)
#define BBUF (BN * PAD * 2)
#define GSM  (2 * (ABUF + BBUF))    // 61440 B dynamic smem
#define N_ITERS 16                  // 512 / 32

__global__ __launch_bounds__(256, 1) void gemm_mma_kernel(
    const float* __restrict__ X, int bx)
{
    extern __shared__ __align__(16) char sm[];
    const uint32_t aSm = smem_u32(sm);
    const uint32_t bSm = aSm + 2 * ABUF;

    const int tid = threadIdx.x;
    const int wid = tid >> 5, lid = tid & 31;
    const int wr = wid >> 2, wc = wid & 3;
    const int by = blockIdx.x;                 // M tile: 0..390

    float acc[4][8][4];
#pragma unroll
    for (int mi = 0; mi < 4; mi++)
#pragma unroll
        for (int nj = 0; nj < 8; nj++)
#pragma unroll
            for (int q = 0; q < 4; q++) acc[mi][nj][q] = 0.0f;

    float4 aReg[4];

#define LDG_A(it) do {                                                            \
        const int _k0 = (it) * BK;                                                \
        _Pragma("unroll")                                                         \
        for (int _j = 0; _j < 4; _j++) {                                          \
            const int _p = tid + _j * 256;                                        \
            const int _r = _p >> 3, _c = (_p & 7) * 4;                            \
            const int _gr = by * BM + _r;                                         \
            aReg[_j] = (_gr < N_NODES)                                            \
                ? *(const float4*)(X + (size_t)_gr * D_FEAT + _k0 + _c)           \
                : make_float4(0.f, 0.f, 0.f, 0.f);                                \
        }                                                                         \
    } while (0)

#define STS_A(buf) do {                                                           \
        _Pragma("unroll")                                                         \
        for (int _j = 0; _j < 4; _j++) {                                          \
            const int _p = tid + _j * 256;                                        \
            const int _r = _p >> 3, _c = (_p & 7) * 4;                            \
            __half2 _h0 = __float22half2_rn(make_float2(aReg[_j].x, aReg[_j].y)); \
            __half2 _h1 = __float22half2_rn(make_float2(aReg[_j].z, aReg[_j].w)); \
            *(uint2*)(sm + (buf) * ABUF + (uint32_t)(_r * PAD + _c) * 2) =        \
                make_uint2(*(uint32_t*)&_h0, *(uint32_t*)&_h1);                   \
        }                                                                         \
    } while (0)

#define LOAD_B(it, buf) do {                                                      \
        const int _k0 = (it) * BK;                                                \
        const __half* _Bp = g_Wt + (size_t)(bx * BN) * D_FEAT + _k0;              \
        _Pragma("unroll")                                                         \
        for (int _j = 0; _j < 4; _j++) {                                          \
            const int _p = tid + _j * 256;                                        \
            const int _r = _p >> 2, _c = (_p & 3) * 8;                            \
            cp_async16(bSm + (buf) * BBUF + (uint32_t)(_r * PAD + _c) * 2,        \
                       _Bp + (size_t)_r * D_FEAT + _c);                           \
        }                                                                         \
        CP_COMMIT();                                                              \
    } while (0)

    LDG_A(0);
    LOAD_B(0, 0);

    const int lrow = lid & 15;
    const int lcol8 = (lid >> 4) * 8;

#pragma unroll 1
    for (int it = 0; it < N_ITERS; it++) {
        const int b = it & 1;
        STS_A(b);
        if (it + 1 < N_ITERS) {
            LDG_A(it + 1);
            LOAD_B(it + 1, b ^ 1);
            CP_WAIT(1);
        } else {
            CP_WAIT(0);
        }
        __syncthreads();

#pragma unroll
        for (int ks = 0; ks < BK; ks += 16) {
            uint32_t af[4][4];
#pragma unroll
            for (int mi = 0; mi < 4; mi++) {
                const uint32_t addr = aSm + b * ABUF +
                    (uint32_t)((wr * 64 + mi * 16 + lrow) * PAD + ks + lcol8) * 2;
                LDMATRIX_X4(af[mi][0], af[mi][1], af[mi][2], af[mi][3], addr);
            }
            uint32_t bf[4][4];
#pragma unroll
            for (int nh = 0; nh < 4; nh++) {
                const uint32_t addr = bSm + b * BBUF +
                    (uint32_t)((wc * 64 + nh * 16 + lrow) * PAD + ks + lcol8) * 2;
                LDMATRIX_X4(bf[nh][0], bf[nh][1], bf[nh][2], bf[nh][3], addr);
            }
#pragma unroll
            for (int mi = 0; mi < 4; mi++)
#pragma unroll
                for (int nj = 0; nj < 8; nj++) {
                    const uint32_t b0 = bf[nj >> 1][(nj & 1)];
                    const uint32_t b1 = bf[nj >> 1][(nj & 1) + 2];
                    mma16816_f16(acc[mi][nj], af[mi], b0, b1);
                }
        }
        __syncthreads();
    }

    const int qrow = lid >> 2;
    const int qcol = (lid & 3) * 2;
#pragma unroll
    for (int mi = 0; mi < 4; mi++) {
        const size_t r0 = (size_t)by * BM + wr * 64 + mi * 16 + qrow;
#pragma unroll
        for (int nj = 0; nj < 8; nj++) {
            const int c0 = bx * BN + wc * 64 + nj * 8 + qcol;
            *(__half2*)(g_hh + r0 * UNITS + c0) =
                __float22half2_rn(make_float2(acc[mi][nj][0], acc[mi][nj][1]));
            *(__half2*)(g_hh + (r0 + 8) * UNITS + c0) =
                __float22half2_rn(make_float2(acc[mi][nj][2], acc[mi][nj][3]));
        }
    }
}

// ---------------------------------------------------------------------------
// Aggregate over a 256-column half. One block (64 threads) per dst row.
// fp16 gather, fp32 accumulate, fused bias + ReLU. 8-way edge unroll.
// ---------------------------------------------------------------------------
__global__ __launch_bounds__(64) void aggregate_half_kernel(
    const float* __restrict__ bias, float* __restrict__ out, int colbase4)
{
    const int d = blockIdx.x;
    const int c = colbase4 + threadIdx.x;
    const int beg = g_off[d];
    const int end = g_off[d + 1];

    const uint2* __restrict__ h2 = (const uint2*)g_hh;
    float4 acc = make_float4(0.f, 0.f, 0.f, 0.f);

#define ACC_EDGE(sw) do {                                                     \
        const uint2 u = __ldg(&h2[(size_t)(sw).x * (UNITS / 4) + c]);         \
        const float w = __int_as_float((sw).y);                               \
        const float2 f0 = __half22float2(*(const __half2*)&u.x);              \
        const float2 f1 = __half22float2(*(const __half2*)&u.y);              \
        acc.x = fmaf(w, f0.x, acc.x); acc.y = fmaf(w, f0.y, acc.y);           \
        acc.z = fmaf(w, f1.x, acc.z); acc.w = fmaf(w, f1.y, acc.w);           \
    } while (0)

    int e = beg;
    for (; e + 7 < end; e += 8) {
        int2 sw[8];
#pragma unroll
        for (int q = 0; q < 8; q++) sw[q] = g_sorted[e + q];
#pragma unroll
        for (int q = 0; q < 8; q++) ACC_EDGE(sw[q]);
    }
    for (; e + 3 < end; e += 4) {
        int2 sw[4];
#pragma unroll
        for (int q = 0; q < 4; q++) sw[q] = g_sorted[e + q];
#pragma unroll
        for (int q = 0; q < 4; q++) ACC_EDGE(sw[q]);
    }
    for (; e < end; e++) {
        const int2 sw = g_sorted[e];
        ACC_EDGE(sw);
    }

    const float4 b = ((const float4*)bias)[c];
    float4 r;
    r.x = fmaxf(acc.x + b.x, 0.0f);
    r.y = fmaxf(acc.y + b.y, 0.0f);
    r.z = fmaxf(acc.z + b.z, 0.0f);
    r.w = fmaxf(acc.w + b.w, 0.0f);
    ((float4*)out)[(size_t)d * (UNITS / 4) + c] = r;
}

// ---------------------------------------------------------------------------
extern "C" void kernel_launch(void* const* d_in, const int* in_sizes, int n_in,
                              void* d_out, int out_size)
{
    const float* X    = (const float*)d_in[0];
    const float* W    = (const float*)d_in[1];
    const float* bias = (const float*)d_in[2];
    const float* ew   = (const float*)d_in[3];
    const void*  es   = d_in[4];
    const void*  ed   = d_in[5];
    float* out = (float*)d_out;

    // One-time host-side setup (pre-capture correctness call; no device alloc).
    static cudaStream_t s_csr = nullptr, s_agg = nullptr;
    static cudaEvent_t evFork = nullptr, evCSR = nullptr, evG0 = nullptr,
                       evG1 = nullptr, evA = nullptr;
    if (!s_csr) {
        cudaStreamCreateWithFlags(&s_csr, cudaStreamNonBlocking);
        cudaStreamCreateWithFlags(&s_agg, cudaStreamNonBlocking);
        cudaEventCreateWithFlags(&evFork, cudaEventDisableTiming);
        cudaEventCreateWithFlags(&evCSR, cudaEventDisableTiming);
        cudaEventCreateWithFlags(&evG0, cudaEventDisableTiming);
        cudaEventCreateWithFlags(&evG1, cudaEventDisableTiming);
        cudaEventCreateWithFlags(&evA, cudaEventDisableTiming);
        cudaFuncSetAttribute(gemm_mma_kernel,
                             cudaFuncAttributeMaxDynamicSharedMemorySize, GSM);
    }

    // ---- fork ----
    cudaEventRecord(evFork, 0);
    cudaStreamWaitEvent(s_csr, evFork, 0);
    cudaStreamWaitEvent(s_agg, evFork, 0);

    // branch A (s_csr): CSR build (rank-saving hist; atomic-free place)
    zero_kernel<<<196, 256, 0, s_csr>>>();
    hist_kernel<<<1024, 256, 0, s_csr>>>(ed);
    scan_lookback_kernel<<<SCAN_NB, SCAN_T, 0, s_csr>>>();
    place_kernel<<<1024, 256, 0, s_csr>>>(es, ed, ew);
    cudaEventRecord(evCSR, s_csr);

    // branch B (main): tiny W convert, then GEMM halves (A conv fused in)
    conv_W_kernel<<<256, 256>>>(W);
    gemm_mma_kernel<<<N_PAD / BM, 256, GSM>>>(X, 0);
    cudaEventRecord(evG0, 0);
    gemm_mma_kernel<<<N_PAD / BM, 256, GSM>>>(X, 1);
    cudaEventRecord(evG1, 0);

    // branch C (s_agg): aggregate halves, sequential
    cudaStreamWaitEvent(s_agg, evG0, 0);
    cudaStreamWaitEvent(s_agg, evCSR, 0);
    aggregate_half_kernel<<<N_NODES, 64, 0, s_agg>>>(bias, out, 0);
    cudaStreamWaitEvent(s_agg, evG1, 0);
    aggregate_half_kernel<<<N_NODES, 64, 0, s_agg>>>(bias, out, 64);
    cudaEventRecord(evA, s_agg);

    // main joins
    cudaStreamWaitEvent(0, evA, 0);
}